// round 12
// baseline (speedup 1.0000x reference)
#include <cuda_runtime.h>
#include <cuda_fp16.h>
#include <cstdint>

// CategorySpecificLinear, round 12:
//  pass 1: ONE fused convert kernel (x + used-cat W -> fp16 scratch),
//          one chunk (8 floats) per thread, inline cat-usage check.
//  pass 2: GEMM (r8/r11 config, NBUF=5 ring): cp.async fp16, 128 thr,
//          64x64 warp tiles, ldmatrix + mma m16n8k16, batch-outermost grid.
// out[b] = x[b] @ W[cat_ids[b]] + bias[cat_ids[b]]

#define B_DIM 64
#define T_DIM 256
#define K_DIM 1024
#define N_DIM 2048
#define NCAT  32

#define TM 128
#define TN 128
#define TK 32
#define STAGES (K_DIM / TK)      // 32
#define NBUF 5
#define NTHREADS 128

// A tile: 128 rows x 32 k f16 = 64B/row, SW128 swizzled.
#define A_STAGE_BYTES (128 * 64)             // 8192
// B tile: 32 k-rows x 128 n f16, row = 256B + 16B pad = 272B.
#define B_ROW_BYTES 272
#define B_STAGE_BYTES (32 * B_ROW_BYTES)     // 8704
#define STAGE_BYTES (A_STAGE_BYTES + B_STAGE_BYTES)  // 16896
#define SMEM_BYTES (NBUF * STAGE_BYTES)      // 84480 -> 2 CTAs/SM

// convert-kernel geometry: one 16B-out chunk (8 fp32 in) per thread
#define NX8 ((B_DIM * T_DIM * K_DIM) / 8)    // 2,097,152 x-chunks
#define NW8_PER_CAT ((K_DIM * N_DIM) / 8)    // 262,144 W-chunks per cat
#define CVT_THREADS 256
#define X_BLOCKS (NX8 / CVT_THREADS)                 // 8192
#define W_BLOCKS_PER_CAT (NW8_PER_CAT / CVT_THREADS) // 1024
#define CVT_BLOCKS (X_BLOCKS + NCAT * W_BLOCKS_PER_CAT) // 40960

__device__ __half g_xh[(size_t)B_DIM * T_DIM * K_DIM];   // 32 MiB
__device__ __half g_wh[(size_t)NCAT * K_DIM * N_DIM];    // 128 MiB

static __device__ __forceinline__ uint32_t sw(uint32_t b) { return b ^ ((b >> 3) & 0x70); }

static __device__ __forceinline__ uint32_t packh2(float lo, float hi) {
    uint32_t r;
    asm("cvt.rn.f16x2.f32 %0, %1, %2;" : "=r"(r) : "f"(hi), "f"(lo));
    return r;
}

static __device__ __forceinline__ void cpasync16(uint32_t dst, const void* src) {
    asm volatile("cp.async.cg.shared.global [%0], [%1], 16;" :: "r"(dst), "l"(src));
}

static __device__ __forceinline__ void ldsm_x4(uint32_t (&r)[4], uint32_t addr) {
    asm volatile("ldmatrix.sync.aligned.m8n8.x4.shared.b16 {%0,%1,%2,%3}, [%4];"
                 : "=r"(r[0]), "=r"(r[1]), "=r"(r[2]), "=r"(r[3]) : "r"(addr));
}
static __device__ __forceinline__ void ldsm_x4_trans(uint32_t (&r)[4], uint32_t addr) {
    asm volatile("ldmatrix.sync.aligned.m8n8.x4.trans.shared.b16 {%0,%1,%2,%3}, [%4];"
                 : "=r"(r[0]), "=r"(r[1]), "=r"(r[2]), "=r"(r[3]) : "r"(addr));
}

static __device__ __forceinline__ void mma_f16(float (&d)[4],
                                               const uint32_t (&a)[4],
                                               const uint32_t* b) {
    asm volatile(
        "mma.sync.aligned.m16n8k16.row.col.f32.f16.f16.f32 "
        "{%0,%1,%2,%3}, {%4,%5,%6,%7}, {%8,%9}, {%0,%1,%2,%3};"
        : "+f"(d[0]), "+f"(d[1]), "+f"(d[2]), "+f"(d[3])
        : "r"(a[0]), "r"(a[1]), "r"(a[2]), "r"(a[3]), "r"(b[0]), "r"(b[1]));
}

// ---------------- fused convert: x and used-cat W -> fp16 -------------------
__global__ void __launch_bounds__(CVT_THREADS)
cvt_all(const float* __restrict__ x, const float* __restrict__ W,
        const int* __restrict__ cat_ids)
{
    const int bid = blockIdx.x;
    const int tid = threadIdx.x;

    const float* src;
    __half* dst;
    size_t chunk;

    if (bid < X_BLOCKS) {
        chunk = (size_t)bid * CVT_THREADS + tid;
        src = x;
        dst = g_xh;
    } else {
        const int wb  = bid - X_BLOCKS;
        const int cat = wb / W_BLOCKS_PER_CAT;
        // inline usage check: one thread scans cat_ids (256B, L1-resident)
        __shared__ int used;
        if (tid == 0) {
            int u = 0;
            for (int i = 0; i < B_DIM; i++) u |= (cat_ids[i] == cat);
            used = u;
        }
        __syncthreads();
        if (!used) return;
        chunk = (size_t)wb * CVT_THREADS + tid;   // global W chunk index
        src = W;
        dst = g_wh;
    }

    float4 a = ((const float4*)src)[2 * chunk];
    float4 b = ((const float4*)src)[2 * chunk + 1];
    uint4 o;
    o.x = packh2(a.x, a.y);
    o.y = packh2(a.z, a.w);
    o.z = packh2(b.x, b.y);
    o.w = packh2(b.z, b.w);
    ((uint4*)dst)[chunk] = o;
}

// ---------------- GEMM (r8/r11 config, NBUF=5) -------------------------------
__global__ void __launch_bounds__(NTHREADS, 2)
cat_linear_mma(const int* __restrict__ cat_ids,
               const float* __restrict__ bias,
               float* __restrict__ out)
{
    extern __shared__ char smraw[];
    const uint32_t smbase = (uint32_t)__cvta_generic_to_shared(smraw);

    const int tid  = threadIdx.x;
    const int wid  = tid >> 5;
    const int lane = tid & 31;
    const int wm   = wid >> 1;        // 0..1 (M half)
    const int wn   = wid & 1;         // 0..1 (N half)
    const int fr   = lane >> 2;       // 0..7
    const int fc   = lane & 3;        // 0..3

    const int bn    = blockIdx.x;     // 0..15
    const int bm    = blockIdx.y;     // 0..1
    const int batch = blockIdx.z;     // 0..63
    const int n0    = bn * TN;
    const int cat   = cat_ids[batch];

    const __half* Ap = g_xh + (size_t)batch * T_DIM * K_DIM + (size_t)bm * TM * K_DIM;
    const __half* Bp = g_wh + (size_t)cat * K_DIM * N_DIM + n0;

    // cp.async maps (16B granules):
    const int am0 = tid >> 2;          // A: m=(tid>>2)+32i, c=tid&3
    const int acx = tid & 3;
    const int bk0 = tid >> 4;          // B: k=(tid>>4)+8i, c=tid&15
    const int bcx = tid & 15;

    // ldmatrix per-lane address components
    const int q_row = (lane & 7) + 8 * ((lane >> 3) & 1);
    const int q_hi  = (lane >> 4);
    const uint32_t a_pre = (uint32_t)((wm * 64 + q_row) * 64 + 16 * q_hi);
    const uint32_t b_pre = (uint32_t)(q_row * B_ROW_BYTES + (wn * 64 + 8 * q_hi) * 2);

    float acc[4][8][4];
#pragma unroll
    for (int m = 0; m < 4; m++)
#pragma unroll
        for (int n = 0; n < 8; n++)
#pragma unroll
            for (int j = 0; j < 4; j++) acc[m][n][j] = 0.f;

    auto issue_stage = [&](int s, int buf) {
        const uint32_t abase = smbase + (uint32_t)buf * STAGE_BYTES;
        const uint32_t bbase = abase + A_STAGE_BYTES;
        const int k0 = s * TK;
#pragma unroll
        for (int i = 0; i < 4; i++) {
            int m = am0 + 32 * i;
            cpasync16(abase + sw((uint32_t)m * 64u + (uint32_t)acx * 16u),
                      Ap + (size_t)m * K_DIM + k0 + acx * 8);
        }
#pragma unroll
        for (int i = 0; i < 4; i++) {
            int k = bk0 + 8 * i;
            cpasync16(bbase + (uint32_t)k * B_ROW_BYTES + (uint32_t)bcx * 16u,
                      Bp + (size_t)(k0 + k) * N_DIM + bcx * 8);
        }
    };

    // prologue: 4 stages in flight
    issue_stage(0, 0);
    asm volatile("cp.async.commit_group;" ::: "memory");
    issue_stage(1, 1);
    asm volatile("cp.async.commit_group;" ::: "memory");
    issue_stage(2, 2);
    asm volatile("cp.async.commit_group;" ::: "memory");
    issue_stage(3, 3);
    asm volatile("cp.async.commit_group;" ::: "memory");

    for (int s = 0; s < STAGES; s++) {
        asm volatile("cp.async.wait_group 3;" ::: "memory");
        __syncthreads();

        // refill: buffer (s+4)%5 held stage s-1, done by all warps at barrier
        if (s + 4 < STAGES)
            issue_stage(s + 4, (s + 4) % NBUF);
        asm volatile("cp.async.commit_group;" ::: "memory");

        const uint32_t abase = smbase + (uint32_t)(s % NBUF) * STAGE_BYTES;
        const uint32_t bbase = abase + A_STAGE_BYTES;

#pragma unroll
        for (int kb = 0; kb < TK; kb += 16) {
            uint32_t af[4][4], bf[4][4];
#pragma unroll
            for (int mt = 0; mt < 4; mt++)
                ldsm_x4(af[mt], abase + sw(a_pre + (uint32_t)(mt * 16 * 64) + (uint32_t)(kb * 2)));
#pragma unroll
            for (int g = 0; g < 4; g++)
                ldsm_x4_trans(bf[g], bbase + b_pre + (uint32_t)(kb * B_ROW_BYTES) + (uint32_t)(g * 32));
#pragma unroll
            for (int m = 0; m < 4; m++)
#pragma unroll
                for (int n = 0; n < 8; n++)
                    mma_f16(acc[m][n], af[m], &bf[n >> 1][(n & 1) * 2]);
        }
    }

    // epilogue: add bias, store
    {
        const float* brow = bias + (size_t)cat * N_DIM;
        float* obase = out + (size_t)batch * T_DIM * N_DIM;
#pragma unroll
        for (int m = 0; m < 4; m++) {
            int row = bm * TM + wm * 64 + m * 16 + fr;
#pragma unroll
            for (int n = 0; n < 8; n++) {
                int col = n0 + wn * 64 + n * 8 + fc * 2;
                float2 bv = *(const float2*)(brow + col);
                float2 o0, o1;
                o0.x = acc[m][n][0] + bv.x;
                o0.y = acc[m][n][1] + bv.y;
                o1.x = acc[m][n][2] + bv.x;
                o1.y = acc[m][n][3] + bv.y;
                *(float2*)(obase + (size_t)row * N_DIM + col)       = o0;
                *(float2*)(obase + (size_t)(row + 8) * N_DIM + col) = o1;
            }
        }
    }
}

extern "C" void kernel_launch(void* const* d_in, const int* in_sizes, int n_in,
                              void* d_out, int out_size)
{
    const float* x       = (const float*)d_in[0];
    const int*   cat_ids = (const int*)  d_in[1];
    const float* W       = (const float*)d_in[2];
    const float* bias    = (const float*)d_in[3];
    float*       out     = (float*)d_out;

    cvt_all<<<CVT_BLOCKS, CVT_THREADS>>>(x, W, cat_ids);

    cudaFuncSetAttribute(cat_linear_mma, cudaFuncAttributeMaxDynamicSharedMemorySize, SMEM_BYTES);
    dim3 grid(N_DIM / TN, T_DIM / TM, B_DIM);   // (16, 2, 64): batch outermost
    cat_linear_mma<<<grid, NTHREADS, SMEM_BYTES>>>(cat_ids, bias, out);
}

// round 13
// speedup vs baseline: 1.0278x; 1.0278x over previous
#include <cuda_runtime.h>
#include <cuda_fp16.h>
#include <cstdint>

// CategorySpecificLinear, round 13:
//  pass 1: fused convert (x + used-cat W -> fp16), 4 chunks/thread, MLP=8.
//  pass 2: GEMM = exact round-11 config (TK=32, NBUF=4, 128 thr, 64x64 warp
//          tiles, cp.async fp16 + ldmatrix + mma m16n8k16, batch-outermost).
// out[b] = x[b] @ W[cat_ids[b]] + bias[cat_ids[b]]

#define B_DIM 64
#define T_DIM 256
#define K_DIM 1024
#define N_DIM 2048
#define NCAT  32

#define TM 128
#define TN 128
#define TK 32
#define STAGES (K_DIM / TK)      // 32
#define NBUF 4
#define NTHREADS 128

// A tile: 128 rows x 32 k f16 = 64B/row, SW128 swizzled.
#define A_STAGE_BYTES (128 * 64)             // 8192
// B tile: 32 k-rows x 128 n f16, row = 256B + 16B pad = 272B.
#define B_ROW_BYTES 272
#define B_STAGE_BYTES (32 * B_ROW_BYTES)     // 8704
#define STAGE_BYTES (A_STAGE_BYTES + B_STAGE_BYTES)  // 16896
#define SMEM_BYTES (NBUF * STAGE_BYTES)      // 67584 -> 2 CTAs/SM

// converter geometry: 4 chunks (16B out each) per thread, MLP=8 LDG.128
#define NX8 ((B_DIM * T_DIM * K_DIM) / 8)    // 2,097,152 x-chunks
#define NW8_PER_CAT ((K_DIM * N_DIM) / 8)    // 262,144 W-chunks per cat
#define CVT_THREADS 256
#define CPT 4                                 // chunks per thread
#define X_CVT_BLOCKS (NX8 / (CVT_THREADS * CPT))           // 2048
#define W_CVT_BLOCKS_PER_CAT (NW8_PER_CAT / (CVT_THREADS * CPT))  // 256
#define CVT_BLOCKS (X_CVT_BLOCKS + NCAT * W_CVT_BLOCKS_PER_CAT)   // 10240

__device__ __half g_xh[(size_t)B_DIM * T_DIM * K_DIM];   // 32 MiB
__device__ __half g_wh[(size_t)NCAT * K_DIM * N_DIM];    // 128 MiB

static __device__ __forceinline__ uint32_t sw(uint32_t b) { return b ^ ((b >> 3) & 0x70); }

static __device__ __forceinline__ uint32_t packh2(float lo, float hi) {
    uint32_t r;
    asm("cvt.rn.f16x2.f32 %0, %1, %2;" : "=r"(r) : "f"(hi), "f"(lo));
    return r;
}

static __device__ __forceinline__ void cpasync16(uint32_t dst, const void* src) {
    asm volatile("cp.async.cg.shared.global [%0], [%1], 16;" :: "r"(dst), "l"(src));
}

static __device__ __forceinline__ void ldsm_x4(uint32_t (&r)[4], uint32_t addr) {
    asm volatile("ldmatrix.sync.aligned.m8n8.x4.shared.b16 {%0,%1,%2,%3}, [%4];"
                 : "=r"(r[0]), "=r"(r[1]), "=r"(r[2]), "=r"(r[3]) : "r"(addr));
}
static __device__ __forceinline__ void ldsm_x4_trans(uint32_t (&r)[4], uint32_t addr) {
    asm volatile("ldmatrix.sync.aligned.m8n8.x4.trans.shared.b16 {%0,%1,%2,%3}, [%4];"
                 : "=r"(r[0]), "=r"(r[1]), "=r"(r[2]), "=r"(r[3]) : "r"(addr));
}

static __device__ __forceinline__ void mma_f16(float (&d)[4],
                                               const uint32_t (&a)[4],
                                               const uint32_t* b) {
    asm volatile(
        "mma.sync.aligned.m16n8k16.row.col.f32.f16.f16.f32 "
        "{%0,%1,%2,%3}, {%4,%5,%6,%7}, {%8,%9}, {%0,%1,%2,%3};"
        : "+f"(d[0]), "+f"(d[1]), "+f"(d[2]), "+f"(d[3])
        : "r"(a[0]), "r"(a[1]), "r"(a[2]), "r"(a[3]), "r"(b[0]), "r"(b[1]));
}

// ---------------- fused convert: x and used-cat W -> fp16, MLP=8 ------------
__global__ void __launch_bounds__(CVT_THREADS)
cvt_all(const float* __restrict__ x, const float* __restrict__ W,
        const int* __restrict__ cat_ids)
{
    const int bid = blockIdx.x;
    const int tid = threadIdx.x;

    const float* src;
    __half* dst;
    size_t base;   // first chunk index; thread covers base + i*CVT_THREADS

    if (bid < X_CVT_BLOCKS) {
        base = (size_t)bid * (CVT_THREADS * CPT) + tid;
        src = x;
        dst = g_xh;
    } else {
        const int wb  = bid - X_CVT_BLOCKS;
        const int cat = wb / W_CVT_BLOCKS_PER_CAT;
        __shared__ int used;
        if (tid == 0) {
            int u = 0;
#pragma unroll
            for (int i = 0; i < B_DIM; i++) u |= (cat_ids[i] == cat);
            used = u;
        }
        __syncthreads();
        if (!used) return;
        base = (size_t)wb * (CVT_THREADS * CPT) + tid;
        src = W;
        dst = g_wh;
    }

    // issue all 8 LDG.128 before any dependent work (MLP=8)
    float4 a[CPT], b[CPT];
#pragma unroll
    for (int i = 0; i < CPT; i++) {
        size_t c = base + (size_t)i * CVT_THREADS;
        a[i] = ((const float4*)src)[2 * c];
        b[i] = ((const float4*)src)[2 * c + 1];
    }
#pragma unroll
    for (int i = 0; i < CPT; i++) {
        size_t c = base + (size_t)i * CVT_THREADS;
        uint4 o;
        o.x = packh2(a[i].x, a[i].y);
        o.y = packh2(a[i].z, a[i].w);
        o.z = packh2(b[i].x, b[i].y);
        o.w = packh2(b[i].z, b[i].w);
        ((uint4*)dst)[c] = o;
    }
}

// ---------------- GEMM (exact round-11 configuration) -----------------------
__global__ void __launch_bounds__(NTHREADS, 2)
cat_linear_mma(const int* __restrict__ cat_ids,
               const float* __restrict__ bias,
               float* __restrict__ out)
{
    extern __shared__ char smraw[];
    const uint32_t smbase = (uint32_t)__cvta_generic_to_shared(smraw);

    const int tid  = threadIdx.x;
    const int wid  = tid >> 5;
    const int lane = tid & 31;
    const int wm   = wid >> 1;        // 0..1 (M half)
    const int wn   = wid & 1;         // 0..1 (N half)
    const int fr   = lane >> 2;       // 0..7
    const int fc   = lane & 3;        // 0..3

    const int bn    = blockIdx.x;     // 0..15
    const int bm    = blockIdx.y;     // 0..1
    const int batch = blockIdx.z;     // 0..63
    const int n0    = bn * TN;
    const int cat   = cat_ids[batch];

    const __half* Ap = g_xh + (size_t)batch * T_DIM * K_DIM + (size_t)bm * TM * K_DIM;
    const __half* Bp = g_wh + (size_t)cat * K_DIM * N_DIM + n0;

    // cp.async maps (16B granules):
    const int am0 = tid >> 2;          // A: m=(tid>>2)+32i, c=tid&3
    const int acx = tid & 3;
    const int bk0 = tid >> 4;          // B: k=(tid>>4)+8i, c=tid&15
    const int bcx = tid & 15;

    // ldmatrix per-lane address components
    const int q_row = (lane & 7) + 8 * ((lane >> 3) & 1);
    const int q_hi  = (lane >> 4);
    const uint32_t a_pre = (uint32_t)((wm * 64 + q_row) * 64 + 16 * q_hi);
    const uint32_t b_pre = (uint32_t)(q_row * B_ROW_BYTES + (wn * 64 + 8 * q_hi) * 2);

    float acc[4][8][4];
#pragma unroll
    for (int m = 0; m < 4; m++)
#pragma unroll
        for (int n = 0; n < 8; n++)
#pragma unroll
            for (int j = 0; j < 4; j++) acc[m][n][j] = 0.f;

    auto issue_stage = [&](int s, int buf) {
        const uint32_t abase = smbase + (uint32_t)buf * STAGE_BYTES;
        const uint32_t bbase = abase + A_STAGE_BYTES;
        const int k0 = s * TK;
#pragma unroll
        for (int i = 0; i < 4; i++) {
            int m = am0 + 32 * i;
            cpasync16(abase + sw((uint32_t)m * 64u + (uint32_t)acx * 16u),
                      Ap + (size_t)m * K_DIM + k0 + acx * 8);
        }
#pragma unroll
        for (int i = 0; i < 4; i++) {
            int k = bk0 + 8 * i;
            cpasync16(bbase + (uint32_t)k * B_ROW_BYTES + (uint32_t)bcx * 16u,
                      Bp + (size_t)(k0 + k) * N_DIM + bcx * 8);
        }
    };

    // prologue: 3 stages in flight
    issue_stage(0, 0);
    asm volatile("cp.async.commit_group;" ::: "memory");
    issue_stage(1, 1);
    asm volatile("cp.async.commit_group;" ::: "memory");
    issue_stage(2, 2);
    asm volatile("cp.async.commit_group;" ::: "memory");

    for (int s = 0; s < STAGES; s++) {
        asm volatile("cp.async.wait_group 2;" ::: "memory");
        __syncthreads();

        // refill: buffer (s+3)%4 held stage s-1, done by all warps at barrier
        if (s + 3 < STAGES)
            issue_stage(s + 3, (s + 3) % NBUF);
        asm volatile("cp.async.commit_group;" ::: "memory");

        const uint32_t abase = smbase + (uint32_t)(s % NBUF) * STAGE_BYTES;
        const uint32_t bbase = abase + A_STAGE_BYTES;

#pragma unroll
        for (int kb = 0; kb < TK; kb += 16) {
            uint32_t af[4][4], bf[4][4];
#pragma unroll
            for (int mt = 0; mt < 4; mt++)
                ldsm_x4(af[mt], abase + sw(a_pre + (uint32_t)(mt * 16 * 64) + (uint32_t)(kb * 2)));
#pragma unroll
            for (int g = 0; g < 4; g++)
                ldsm_x4_trans(bf[g], bbase + b_pre + (uint32_t)(kb * B_ROW_BYTES) + (uint32_t)(g * 32));
#pragma unroll
            for (int m = 0; m < 4; m++)
#pragma unroll
                for (int n = 0; n < 8; n++)
                    mma_f16(acc[m][n], af[m], &bf[n >> 1][(n & 1) * 2]);
        }
    }

    // epilogue: add bias, store
    {
        const float* brow = bias + (size_t)cat * N_DIM;
        float* obase = out + (size_t)batch * T_DIM * N_DIM;
#pragma unroll
        for (int m = 0; m < 4; m++) {
            int row = bm * TM + wm * 64 + m * 16 + fr;
#pragma unroll
            for (int n = 0; n < 8; n++) {
                int col = n0 + wn * 64 + n * 8 + fc * 2;
                float2 bv = *(const float2*)(brow + col);
                float2 o0, o1;
                o0.x = acc[m][n][0] + bv.x;
                o0.y = acc[m][n][1] + bv.y;
                o1.x = acc[m][n][2] + bv.x;
                o1.y = acc[m][n][3] + bv.y;
                *(float2*)(obase + (size_t)row * N_DIM + col)       = o0;
                *(float2*)(obase + (size_t)(row + 8) * N_DIM + col) = o1;
            }
        }
    }
}

extern "C" void kernel_launch(void* const* d_in, const int* in_sizes, int n_in,
                              void* d_out, int out_size)
{
    const float* x       = (const float*)d_in[0];
    const int*   cat_ids = (const int*)  d_in[1];
    const float* W       = (const float*)d_in[2];
    const float* bias    = (const float*)d_in[3];
    float*       out     = (float*)d_out;

    cvt_all<<<CVT_BLOCKS, CVT_THREADS>>>(x, W, cat_ids);

    cudaFuncSetAttribute(cat_linear_mma, cudaFuncAttributeMaxDynamicSharedMemorySize, SMEM_BYTES);
    dim3 grid(N_DIM / TN, T_DIM / TM, B_DIM);   // (16, 2, 64): batch outermost
    cat_linear_mma<<<grid, NTHREADS, SMEM_BYTES>>>(cat_ids, bias, out);
}